// round 9
// baseline (speedup 1.0000x reference)
#include <cuda_runtime.h>
#include <cuda_bf16.h>

#define FULLMASK 0xffffffffu
#define TT 4096
#define NB 128          // blocks (1/SM -> grid barrier co-residency guaranteed)
#define NR 16           // rows per block = warps per block (1 warp per row)

// ---- device scratch (allocation-free, zero-init) ----
__device__ volatile unsigned g_arr[3][NB];   // per-block arrival flags
__device__ volatile unsigned g_rel[3];       // release words
__device__ float g_p0[NB][64];   // per-block feature col sum[32] + sumsq[32]
__device__ float g_p1[NB][16];   // per-block h1 sum[8] + sumsq[8]
__device__ float g_p2[NB][16];   // per-block h2 sum[8] + sumsq[8]

// Flag-array grid barrier, graph-replay-safe.
// Arrival: distinct-address stores (no atomic serialization). Block 0 warp 0
// aggregates, resets arrival flags, clears release slot (s+2)%3 (provably
// un-polled: everyone passing barrier s implies everyone passed s-1), then
// sets release s. Ring of 3 slots self-cleans across launches (zero-init).
__device__ __forceinline__ void grid_barrier(int s) {
    __threadfence();
    __syncthreads();
    if (threadIdx.x == 0) g_arr[s][blockIdx.x] = 1u;
    if (blockIdx.x == 0) {
        if (threadIdx.x < 32) {
            const int i0 = threadIdx.x * 4;
            while (!(g_arr[s][i0] & g_arr[s][i0 + 1] &
                     g_arr[s][i0 + 2] & g_arr[s][i0 + 3])) {}
            g_arr[s][i0] = 0u; g_arr[s][i0 + 1] = 0u;
            g_arr[s][i0 + 2] = 0u; g_arr[s][i0 + 3] = 0u;
            __syncwarp();
            if (threadIdx.x == 0) {
                g_rel[(s + 2) % 3] = 0u;
                __threadfence();
                g_rel[s] = 1u;
            }
        }
    } else if (threadIdx.x == 0) {
        while (g_rel[s] == 0u) {}
        __threadfence();
    }
    __syncthreads();
}

__global__ __launch_bounds__(512, 1) void fused_all(
    const float* __restrict__ X,
    const float* __restrict__ features,
    const float* __restrict__ Fp,
    const float* __restrict__ bn0_g, const float* __restrict__ bn0_b,
    const float* __restrict__ W1,    const float* __restrict__ b1,
    const float* __restrict__ bn1_g, const float* __restrict__ bn1_b,
    const float* __restrict__ W2,    const float* __restrict__ b2,
    const float* __restrict__ bn2_g, const float* __restrict__ bn2_b,
    const float* __restrict__ W3,    const float* __restrict__ b3,
    const float* __restrict__ pn,
    float* __restrict__ out)
{
    __shared__ float s_sum[NR][32], s_sq[NR][32];
    __shared__ float s_acc[8][64];
    __shared__ float s_acc2[32][16];
    __shared__ float s_p[NR][16];
    __shared__ float sW1[256], sW2[64], sW3[48];
    __shared__ float sb1[8], sb2[8], sb3[6], spn[6];
    __shared__ float s_sc0[32], s_sh0[32];
    __shared__ float s_sc1[8], s_sh1[8];
    __shared__ float s_sc2[8], s_sh2[8];

    const int tid  = threadIdx.x;
    const int warp = tid >> 5;
    const int lane = tid & 31;
    const int row  = blockIdx.x * NR + warp;
    const float* xrow = X + (size_t)row * TT;

    // ---------- warm L2 with this warp's row (128 lines of 128B) ----------
    #pragma unroll
    for (int k = 0; k < 4; k++)
        asm volatile("prefetch.global.L2 [%0];"
                     :: "l"(xrow + (size_t)(lane + k * 32) * 32) : "memory");

    // ---------- P0: feature load (coalesced: lane = column), bn0 partials ----------
    const float fv = features[(size_t)row * 32 + lane];
    s_sum[warp][lane] = fv;
    s_sq [warp][lane] = fv * fv;
    if (tid < 256) sW1[tid] = W1[tid];
    else if (tid < 320) sW2[tid - 256] = W2[tid - 256];
    else if (tid < 368) sW3[tid - 320] = W3[tid - 320];
    else if (tid < 376) sb1[tid - 368] = b1[tid - 368];
    else if (tid < 384) sb2[tid - 376] = b2[tid - 376];
    else if (tid < 390) sb3[tid - 384] = b3[tid - 384];
    else if (tid < 396) spn[tid - 390] = pn[tid - 390];
    __syncthreads();
    if (tid < 64) {
        float a = 0.f;
        const int hs = tid >> 5, col = tid & 31;
        #pragma unroll
        for (int w = 0; w < NR; w++) a += hs ? s_sq[w][col] : s_sum[w][col];
        g_p0[blockIdx.x][tid] = a;
    }
    grid_barrier(0);

    // ---------- P1: finalize bn0, h1 = bn0(f) @ W1^T + b1, bn1 partials ----------
    {
        const int col = tid & 63, ch = tid >> 6;    // 8 chunks of 16 blocks
        float a = 0.f;
        #pragma unroll
        for (int b = 0; b < 16; b++) a += g_p0[ch * 16 + b][col];
        s_acc[ch][col] = a;
    }
    __syncthreads();
    if (tid < 32) {
        float ss = 0.f, qq = 0.f;
        #pragma unroll
        for (int c = 0; c < 8; c++) { ss += s_acc[c][tid]; qq += s_acc[c][32 + tid]; }
        float mean = ss * (1.f / 2048.f);
        float var  = qq * (1.f / 2048.f) - mean * mean;
        float sc   = bn0_g[tid] * rsqrtf(var + 1e-5f);
        s_sc0[tid] = sc;
        s_sh0[tid] = bn0_b[tid] - mean * sc;
    }
    __syncthreads();

    const float xn = fmaf(fv, s_sc0[lane], s_sh0[lane]);
    float h[8];
    #pragma unroll
    for (int j = 0; j < 8; j++) {
        float a = sW1[j * 32 + lane] * xn;
        #pragma unroll
        for (int d = 16; d; d >>= 1) a += __shfl_xor_sync(FULLMASK, a, d);
        h[j] = a + sb1[j];            // all lanes hold h1_j
    }
    if (lane < 16) s_p[warp][lane] = (lane < 8) ? h[lane] : h[lane - 8] * h[lane - 8];
    __syncthreads();
    if (tid < 16) {
        float a = 0.f;
        #pragma unroll
        for (int w = 0; w < NR; w++) a += s_p[w][tid];
        g_p1[blockIdx.x][tid] = a;
    }
    grid_barrier(1);

    // ---------- P2: finalize bn1, h2 = relu(bn1(h1)) @ W2^T + b2, bn2 partials ----------
    {
        const int v = tid & 15, ch = tid >> 4;      // 32 chunks of 4 blocks
        float a = 0.f;
        #pragma unroll
        for (int b = 0; b < 4; b++) a += g_p1[ch * 4 + b][v];
        s_acc2[ch][v] = a;
    }
    __syncthreads();
    if (tid < 8) {
        float ss = 0.f, qq = 0.f;
        #pragma unroll
        for (int c = 0; c < 32; c++) { ss += s_acc2[c][tid]; qq += s_acc2[c][8 + tid]; }
        float mean = ss * (1.f / 2048.f);
        float var  = qq * (1.f / 2048.f) - mean * mean;
        float sc   = bn1_g[tid] * rsqrtf(var + 1e-5f);
        s_sc1[tid] = sc;
        s_sh1[tid] = bn1_b[tid] - mean * sc;
    }
    __syncthreads();

    float z[8];
    #pragma unroll
    for (int j = 0; j < 8; j++) z[j] = fmaxf(fmaf(h[j], s_sc1[j], s_sh1[j]), 0.f);
    #pragma unroll
    for (int k = 0; k < 8; k++) {
        float a = sb2[k];
        #pragma unroll
        for (int j = 0; j < 8; j++) a = fmaf(sW2[k * 8 + j], z[j], a);
        h[k] = a;                     // h now holds h2 (all lanes)
    }
    __syncthreads();                  // s_p reuse
    if (lane < 16) s_p[warp][lane] = (lane < 8) ? h[lane] : h[lane - 8] * h[lane - 8];
    __syncthreads();
    if (tid < 16) {
        float a = 0.f;
        #pragma unroll
        for (int w = 0; w < NR; w++) a += s_p[w][tid];
        g_p2[blockIdx.x][tid] = a;
    }
    grid_barrier(2);

    // ---------- P3: finalize bn2, corr -> sigmoids -> per-row scan params ----------
    {
        const int v = tid & 15, ch = tid >> 4;
        float a = 0.f;
        #pragma unroll
        for (int b = 0; b < 4; b++) a += g_p2[ch * 4 + b][v];
        s_acc2[ch][v] = a;
    }
    __syncthreads();
    if (tid < 8) {
        float ss = 0.f, qq = 0.f;
        #pragma unroll
        for (int c = 0; c < 32; c++) { ss += s_acc2[c][tid]; qq += s_acc2[c][8 + tid]; }
        float mean = ss * (1.f / 2048.f);
        float var  = qq * (1.f / 2048.f) - mean * mean;
        float sc   = bn2_g[tid] * rsqrtf(var + 1e-5f);
        s_sc2[tid] = sc;
        s_sh2[tid] = bn2_b[tid] - mean * sc;
    }
    __syncthreads();

    #pragma unroll
    for (int j = 0; j < 8; j++) z[j] = fmaxf(fmaf(h[j], s_sc2[j], s_sh2[j]), 0.f);
    float sg[6];
    #pragma unroll
    for (int j = 0; j < 6; j++) {
        float a = sb3[j] + spn[j];
        #pragma unroll
        for (int k = 0; k < 8; k++) a = fmaf(sW3[j * 8 + k], z[k], a);
        sg[j] = __fdividef(1.f, 1.f + __expf(-a));
    }
    const float f_start = fmaf(4.5f,  sg[0], 0.5f);
    const float f_inf   = fmaf(0.49f, sg[1], 0.01f);
    const float f_decay = 2.f * sg[2];
    const float f_T     = 2.f * sg[3];
    const float w_off   = sg[4];
    const float w_T     = fmaf(0.49f, sg[5], 0.01f);

    const float df  = f_start - f_inf;
    const float lnD = fmaf(-2.30258509f, f_decay, -0.35667494f);  // ln(0.7*0.1^fd)
    const float H   = 10.f * __expf(-2.30258509f * f_T);          // 10*0.1^fT
    const float kf  = __fdividef(lnD, 4096.f * H);
    const float G   = __expf(kf);
    const float z0  = __fdividef(w_off, w_T);
    const float lw  = -__fdividef(1.f, 4096.f * w_T);
    const float R   = __expf(lw);
    const float cc  = 0.16228221f * __ldg(Fp);   // sqrt(2^(1/3)-1)*F/pi

    // ---------- P4: affine-chunked IIR scan + weighted average ----------
    // Lane l scans steps [128l, 128l+128) in closed affine form
    // (transform [[p,0],[r,p]] + offset (q1,q2)); weighted-output
    // accumulators (a1,a2,bt,ws) are affine in the chunk's entry state.
    const int t0 = lane << 7;
    float g = __expf(kf * (float)t0);
    float e = __expf(fmaf(lw, (float)t0, z0));  // may be inf -> w = 0 (correct)
    float xp = __ldcs(xrow + (t0 ? t0 - 1 : 0));

    float p = 1.f, r = 0.f, q1 = 0.f, q2 = 0.f;
    float a1 = 0.f, a2 = 0.f, bt = 0.f, ws = 0.f;

    const float4* xv = (const float4*)(xrow + t0);
    float4 v  = __ldcs(xv);
    float4 vn = __ldcs(xv + 1);
    const float y0 = __shfl_sync(FULLMASK, v.x, 0);

#define STEP(xval) do {                               \
    float w_ = __fdividef(1.f, 1.f + e);              \
    float f_ = fmaf(df, g, f_inf);                    \
    float i_ = __fdividef(1.f, cc + f_);              \
    float b_ = f_ * i_;                               \
    float ap = fmaf(-2.f, b_, 1.f);                   \
    g *= G; e *= R;                                   \
    float m_ = fmaf(b_, ap, b_);                      \
    float xx = (xval) + xp;                           \
    float u1 = b_ * xx;                               \
    float u2 = b_ * u1;                               \
    float pm = m_ * p;                                \
    float t2 = fmaf(m_, q1, u2);                      \
    p = ap * p;                                       \
    r = fmaf(ap, r, pm);                              \
    q1 = fmaf(ap, q1, u1);                            \
    q2 = fmaf(ap, q2, t2);                            \
    a1 = fmaf(w_, r, a1);                             \
    a2 = fmaf(w_, p, a2);                             \
    bt = fmaf(w_, q2, bt);                            \
    ws += w_;                                         \
    xp = (xval);                                      \
  } while (0)

    if (lane == 0) {
        // t = 0: y2_0 = y0 passes through identity -> a2 += w0, ws += w0
        float w0 = __fdividef(1.f, 1.f + e);
        a2 = w0; ws = w0;
        g *= G; e *= R;
        // xp stays X[0] for the t=1 step
    } else {
        STEP(v.x);
    }
    STEP(v.y); STEP(v.z); STEP(v.w);
    #pragma unroll 2
    for (int i = 1; i < 32; i++) {
        float4 vc = vn;
        if (i < 31) vn = __ldcs(xv + i + 1);
        STEP(vc.x); STEP(vc.y); STEP(vc.z); STEP(vc.w);
    }
#undef STEP

    // inclusive scan: compose self with prefix from lower lanes
    #pragma unroll
    for (int d = 1; d < 32; d <<= 1) {
        float pL  = __shfl_up_sync(FULLMASK, p,  d);
        float rL  = __shfl_up_sync(FULLMASK, r,  d);
        float q1L = __shfl_up_sync(FULLMASK, q1, d);
        float q2L = __shfl_up_sync(FULLMASK, q2, d);
        if (lane >= d) {
            float pn2 = p * pL;
            float rn  = fmaf(r, pL, p * rL);
            float q1n = fmaf(p, q1L, q1);
            float q2n = fmaf(r, q1L, fmaf(p, q2L, q2));
            p = pn2; r = rn; q1 = q1n; q2 = q2n;
        }
    }
    // exclusive shift (identity into lane 0)
    float pe  = __shfl_up_sync(FULLMASK, p,  1);
    float re  = __shfl_up_sync(FULLMASK, r,  1);
    float q1e = __shfl_up_sync(FULLMASK, q1, 1);
    float q2e = __shfl_up_sync(FULLMASK, q2, 1);
    if (lane == 0) { pe = 1.f; re = 0.f; q1e = 0.f; q2e = 0.f; }

    const float y1i = fmaf(pe, y0, q1e);
    const float y2i = fmaf(re + pe, y0, q2e);
    float contrib = fmaf(a1, y1i, fmaf(a2, y2i, bt));

    #pragma unroll
    for (int d = 16; d; d >>= 1) {
        contrib += __shfl_xor_sync(FULLMASK, contrib, d);
        ws      += __shfl_xor_sync(FULLMASK, ws, d);
    }
    if (lane == 0) out[row] = contrib / ws;
}

extern "C" void kernel_launch(void* const* d_in, const int* in_sizes, int n_in,
                              void* d_out, int out_size) {
    const float* X        = (const float*)d_in[0];
    const float* features = (const float*)d_in[1];
    const float* F        = (const float*)d_in[2];
    const float* bn0_g    = (const float*)d_in[3];
    const float* bn0_b    = (const float*)d_in[4];
    const float* W1       = (const float*)d_in[5];
    const float* b1       = (const float*)d_in[6];
    const float* bn1_g    = (const float*)d_in[7];
    const float* bn1_b    = (const float*)d_in[8];
    const float* W2       = (const float*)d_in[9];
    const float* b2       = (const float*)d_in[10];
    const float* bn2_g    = (const float*)d_in[11];
    const float* bn2_b    = (const float*)d_in[12];
    const float* W3       = (const float*)d_in[13];
    const float* b3       = (const float*)d_in[14];
    const float* pn       = (const float*)d_in[15];
    float* out = (float*)d_out;

    fused_all<<<NB, 512>>>(X, features, F, bn0_g, bn0_b, W1, b1,
                           bn1_g, bn1_b, W2, b2, bn2_g, bn2_b, W3, b3, pn, out);
}

// round 10
// speedup vs baseline: 1.0198x; 1.0198x over previous
#include <cuda_runtime.h>
#include <cuda_bf16.h>

#define FULLMASK 0xffffffffu
#define TT 4096
#define MB 16            // MLP blocks (tiny grid -> cheap barriers)

// ---- device scratch (allocation-free, zero-init) ----
__device__ volatile unsigned g2_arr[3][MB];
__device__ volatile unsigned g2_rel[3];
__device__ float g_p0[MB][64];    // per-block feature col sum[32] + sumsq[32]
__device__ float g_p1[MB][16];    // per-block h1 sum[8] + sumsq[8]
__device__ float g_p2[MB][16];    // per-block h2 sum[8] + sumsq[8]
__device__ float g_params[2048 * 8];

// 16-block flag barrier, graph-replay-safe: barrier s clears release slot
// (s+1)%3 (its pollers from the previous launch provably finished) before
// setting release s. Three barriers per launch -> every slot cleaned.
__device__ __forceinline__ void mlp_barrier(int s) {
    __threadfence();
    __syncthreads();
    if (threadIdx.x == 0) g2_arr[s][blockIdx.x] = 1u;
    if (blockIdx.x == 0) {
        if (threadIdx.x < MB) {
            while (g2_arr[s][threadIdx.x] == 0u) {}
            g2_arr[s][threadIdx.x] = 0u;
        }
        __syncwarp();
        if (threadIdx.x == 0) {
            g2_rel[(s + 1) % 3] = 0u;
            __threadfence();
            g2_rel[s] = 1u;
        }
    } else if (threadIdx.x == 0) {
        while (g2_rel[s] == 0u) {}
        __threadfence();
    }
    __syncthreads();
}

// ============ Kernel 1: BN-MLP -> per-row scan params (16 x 128) ============
__global__ __launch_bounds__(128) void mlp_kernel(
    const float* __restrict__ features,
    const float* __restrict__ bn0_g, const float* __restrict__ bn0_b,
    const float* __restrict__ W1,    const float* __restrict__ b1,
    const float* __restrict__ bn1_g, const float* __restrict__ bn1_b,
    const float* __restrict__ W2,    const float* __restrict__ b2,
    const float* __restrict__ bn2_g, const float* __restrict__ bn2_b,
    const float* __restrict__ W3,    const float* __restrict__ b3,
    const float* __restrict__ pn)
{
    __shared__ float s_f[128][33];          // raw features, conflict-free pitch
    __shared__ float s_red[4][64];
    __shared__ float s_p[4][16];
    __shared__ float sW1[256], sW2[64], sW3[48];
    __shared__ float sb1[8], sb2[8], sb3[6], spn[6];
    __shared__ float s_sc0[32], s_sh0[32];
    __shared__ float s_sc1[8], s_sh1[8];
    __shared__ float s_sc2[8], s_sh2[8];

    const int tid  = threadIdx.x;
    const int warp = tid >> 5;
    const int lane = tid & 31;

    // stage weights
    if (tid < 128) sW1[tid] = W1[tid];
    sW1[tid + 128] = W1[tid + 128];
    if (tid < 64) sW2[tid] = W2[tid];
    else if (tid < 112) sW3[tid - 64] = W3[tid - 64];
    else if (tid < 120) sb1[tid - 112] = b1[tid - 112];
    if (tid < 8) sb2[tid] = b2[tid];
    else if (tid < 14) sb3[tid - 8] = b3[tid - 8];
    else if (tid < 20) spn[tid - 14] = pn[tid - 14];

    // ---- P0: stage 128 rows of features (coalesced, lane = column), col stats ----
    {
        float ss = 0.f, qq = 0.f;
        const float* fb = features + ((size_t)blockIdx.x * 128 + warp * 32) * 32;
        #pragma unroll 8
        for (int i = 0; i < 32; i++) {
            float v = fb[i * 32 + lane];
            s_f[warp * 32 + i][lane] = v;
            ss += v;
            qq = fmaf(v, v, qq);
        }
        s_red[warp][lane] = ss;
        s_red[warp][32 + lane] = qq;
    }
    __syncthreads();
    if (tid < 64)
        g_p0[blockIdx.x][tid] = s_red[0][tid] + s_red[1][tid] +
                                s_red[2][tid] + s_red[3][tid];
    mlp_barrier(0);

    if (tid < 32) {
        float ss = 0.f, qq = 0.f;
        #pragma unroll
        for (int b = 0; b < MB; b++) { ss += g_p0[b][tid]; qq += g_p0[b][32 + tid]; }
        float mean = ss * (1.f / 2048.f);
        float var  = qq * (1.f / 2048.f) - mean * mean;
        float sc   = bn0_g[tid] * rsqrtf(var + 1e-5f);
        s_sc0[tid] = sc;
        s_sh0[tid] = bn0_b[tid] - mean * sc;
    }
    __syncthreads();

    // ---- P1: thread-per-row h1 = bn0(f) @ W1^T + b1 ----
    float xn[32];
    #pragma unroll
    for (int c = 0; c < 32; c++) xn[c] = fmaf(s_f[tid][c], s_sc0[c], s_sh0[c]);
    float h[8];
    #pragma unroll
    for (int j = 0; j < 8; j++) {
        float a = sb1[j];
        #pragma unroll
        for (int c = 0; c < 32; c++) a = fmaf(sW1[j * 32 + c], xn[c], a);
        h[j] = a;
    }
    {
        float sv[16];
        #pragma unroll
        for (int j = 0; j < 8; j++) { sv[j] = h[j]; sv[8 + j] = h[j] * h[j]; }
        #pragma unroll
        for (int d = 16; d; d >>= 1) {
            #pragma unroll
            for (int j = 0; j < 16; j++) sv[j] += __shfl_xor_sync(FULLMASK, sv[j], d);
        }
        if (lane < 16) s_p[warp][lane] = sv[lane];
    }
    __syncthreads();
    if (tid < 16)
        g_p1[blockIdx.x][tid] = s_p[0][tid] + s_p[1][tid] + s_p[2][tid] + s_p[3][tid];
    mlp_barrier(1);

    if (tid < 8) {
        float ss = 0.f, qq = 0.f;
        #pragma unroll
        for (int b = 0; b < MB; b++) { ss += g_p1[b][tid]; qq += g_p1[b][8 + tid]; }
        float mean = ss * (1.f / 2048.f);
        float var  = qq * (1.f / 2048.f) - mean * mean;
        float sc   = bn1_g[tid] * rsqrtf(var + 1e-5f);
        s_sc1[tid] = sc;
        s_sh1[tid] = bn1_b[tid] - mean * sc;
    }
    __syncthreads();

    // ---- P2: h2 = relu(bn1(h1)) @ W2^T + b2 ----
    float z[8];
    #pragma unroll
    for (int j = 0; j < 8; j++) z[j] = fmaxf(fmaf(h[j], s_sc1[j], s_sh1[j]), 0.f);
    #pragma unroll
    for (int k = 0; k < 8; k++) {
        float a = sb2[k];
        #pragma unroll
        for (int j = 0; j < 8; j++) a = fmaf(sW2[k * 8 + j], z[j], a);
        h[k] = a;
    }
    {
        float sv[16];
        #pragma unroll
        for (int j = 0; j < 8; j++) { sv[j] = h[j]; sv[8 + j] = h[j] * h[j]; }
        #pragma unroll
        for (int d = 16; d; d >>= 1) {
            #pragma unroll
            for (int j = 0; j < 16; j++) sv[j] += __shfl_xor_sync(FULLMASK, sv[j], d);
        }
        if (lane < 16) s_p[warp][lane] = sv[lane];
    }
    __syncthreads();
    if (tid < 16)
        g_p2[blockIdx.x][tid] = s_p[0][tid] + s_p[1][tid] + s_p[2][tid] + s_p[3][tid];
    mlp_barrier(2);

    if (tid < 8) {
        float ss = 0.f, qq = 0.f;
        #pragma unroll
        for (int b = 0; b < MB; b++) { ss += g_p2[b][tid]; qq += g_p2[b][8 + tid]; }
        float mean = ss * (1.f / 2048.f);
        float var  = qq * (1.f / 2048.f) - mean * mean;
        float sc   = bn2_g[tid] * rsqrtf(var + 1e-5f);
        s_sc2[tid] = sc;
        s_sh2[tid] = bn2_b[tid] - mean * sc;
    }
    __syncthreads();

    // ---- P3: corr -> sigmoids -> per-row scan params ----
    #pragma unroll
    for (int j = 0; j < 8; j++) z[j] = fmaxf(fmaf(h[j], s_sc2[j], s_sh2[j]), 0.f);
    float sg[6];
    #pragma unroll
    for (int j = 0; j < 6; j++) {
        float a = sb3[j] + spn[j];
        #pragma unroll
        for (int k = 0; k < 8; k++) a = fmaf(sW3[j * 8 + k], z[k], a);
        sg[j] = __fdividef(1.f, 1.f + __expf(-a));
    }
    const float f_start = fmaf(4.5f,  sg[0], 0.5f);
    const float f_inf   = fmaf(0.49f, sg[1], 0.01f);
    const float f_decay = 2.f * sg[2];
    const float f_T     = 2.f * sg[3];
    const float w_off   = sg[4];
    const float w_T     = fmaf(0.49f, sg[5], 0.01f);

    const float df  = f_start - f_inf;
    const float lnD = fmaf(-2.30258509f, f_decay, -0.35667494f);  // ln(0.7*0.1^fd)
    const float H   = 10.f * __expf(-2.30258509f * f_T);          // 10*0.1^fT
    const float kf  = __fdividef(lnD, 4096.f * H);
    const float G   = __expf(kf);
    const float z0  = __fdividef(w_off, w_T);
    const float lw  = -__fdividef(1.f, 4096.f * w_T);
    const float R   = __expf(lw);

    const int row = blockIdx.x * 128 + tid;
    float4* op = (float4*)(g_params + row * 8);
    op[0] = make_float4(f_inf, df, kf, G);
    op[1] = make_float4(z0, lw, R, 0.f);
}

// ============ Kernel 2: affine-chunked IIR scan + weighted average ============
// One warp per row; lane l scans steps [128l, 128l+128) in closed affine form
// (transform [[p,0],[r,p]] + offset (q1,q2)); weighted-output accumulators
// (a1,a2,bt,ws) are affine in the chunk's entry state. 5-round shfl scan
// composes chunks, butterfly reduce finishes.
__global__ __launch_bounds__(256) void scan_kernel(const float* __restrict__ X,
                                                   const float* __restrict__ Fp,
                                                   float* __restrict__ out) {
    int warp = threadIdx.x >> 5, lane = threadIdx.x & 31;
    int row = blockIdx.x * 8 + warp;
    const float cc = 0.16228221f * __ldg(Fp);   // sqrt(2^(1/3)-1)*F/pi

    const float4 c0 = *(const float4*)(g_params + row * 8);
    const float4 c1 = *(const float4*)(g_params + row * 8 + 4);
    const float f_inf = c0.x, df = c0.y, kf = c0.z, G = c0.w;
    const float z0 = c1.x, lw = c1.y, R = c1.z;

    const float* xrow = X + (size_t)row * TT;
    const int t0 = lane << 7;
    float g = __expf(kf * (float)t0);
    float e = __expf(fmaf(lw, (float)t0, z0));  // may be inf -> w = 0 (correct)
    float xp = xrow[t0 ? t0 - 1 : 0];

    float p = 1.f, r = 0.f, q1 = 0.f, q2 = 0.f;
    float a1 = 0.f, a2 = 0.f, bt = 0.f, ws = 0.f;

    const float4* xv = (const float4*)(xrow + t0);
    float4 v = __ldcs(xv);
    const float y0 = __shfl_sync(FULLMASK, v.x, 0);

#define STEP(xval) do {                               \
    float w_ = __fdividef(1.f, 1.f + e);              \
    float f_ = fmaf(df, g, f_inf);                    \
    float i_ = __fdividef(1.f, cc + f_);              \
    float b_ = f_ * i_;                               \
    float ap = fmaf(-2.f, b_, 1.f);                   \
    g *= G; e *= R;                                   \
    float m_ = fmaf(b_, ap, b_);                      \
    float xx = (xval) + xp;                           \
    float u1 = b_ * xx;                               \
    float u2 = b_ * u1;                               \
    float pm = m_ * p;                                \
    float t2 = fmaf(m_, q1, u2);                      \
    p = ap * p;                                       \
    r = fmaf(ap, r, pm);                              \
    q1 = fmaf(ap, q1, u1);                            \
    q2 = fmaf(ap, q2, t2);                            \
    a1 = fmaf(w_, r, a1);                             \
    a2 = fmaf(w_, p, a2);                             \
    bt = fmaf(w_, q2, bt);                            \
    ws += w_;                                         \
    xp = (xval);                                      \
  } while (0)

    if (lane == 0) {
        // t = 0: y2_0 = y0 passes through identity -> a2 += w0, ws += w0
        float w0 = __fdividef(1.f, 1.f + e);
        a2 = w0; ws = w0;
        g *= G; e *= R;
        // xp stays X[0] for the t=1 step
    } else {
        STEP(v.x);
    }
    STEP(v.y); STEP(v.z); STEP(v.w);
    #pragma unroll 2
    for (int i = 1; i < 32; i++) {
        v = __ldcs(xv + i);
        STEP(v.x); STEP(v.y); STEP(v.z); STEP(v.w);
    }
#undef STEP

    // inclusive scan: compose self with prefix from lower lanes
    #pragma unroll
    for (int d = 1; d < 32; d <<= 1) {
        float pL  = __shfl_up_sync(FULLMASK, p,  d);
        float rL  = __shfl_up_sync(FULLMASK, r,  d);
        float q1L = __shfl_up_sync(FULLMASK, q1, d);
        float q2L = __shfl_up_sync(FULLMASK, q2, d);
        if (lane >= d) {
            float pn2 = p * pL;
            float rn  = fmaf(r, pL, p * rL);
            float q1n = fmaf(p, q1L, q1);
            float q2n = fmaf(r, q1L, fmaf(p, q2L, q2));
            p = pn2; r = rn; q1 = q1n; q2 = q2n;
        }
    }
    // exclusive shift (identity into lane 0)
    float pe  = __shfl_up_sync(FULLMASK, p,  1);
    float re  = __shfl_up_sync(FULLMASK, r,  1);
    float q1e = __shfl_up_sync(FULLMASK, q1, 1);
    float q2e = __shfl_up_sync(FULLMASK, q2, 1);
    if (lane == 0) { pe = 1.f; re = 0.f; q1e = 0.f; q2e = 0.f; }

    const float y1i = fmaf(pe, y0, q1e);
    const float y2i = fmaf(re + pe, y0, q2e);
    float contrib = fmaf(a1, y1i, fmaf(a2, y2i, bt));

    #pragma unroll
    for (int d = 16; d; d >>= 1) {
        contrib += __shfl_xor_sync(FULLMASK, contrib, d);
        ws      += __shfl_xor_sync(FULLMASK, ws, d);
    }
    if (lane == 0) out[row] = contrib / ws;
}

extern "C" void kernel_launch(void* const* d_in, const int* in_sizes, int n_in,
                              void* d_out, int out_size) {
    const float* X        = (const float*)d_in[0];
    const float* features = (const float*)d_in[1];
    const float* F        = (const float*)d_in[2];
    const float* bn0_g    = (const float*)d_in[3];
    const float* bn0_b    = (const float*)d_in[4];
    const float* W1       = (const float*)d_in[5];
    const float* b1       = (const float*)d_in[6];
    const float* bn1_g    = (const float*)d_in[7];
    const float* bn1_b    = (const float*)d_in[8];
    const float* W2       = (const float*)d_in[9];
    const float* b2       = (const float*)d_in[10];
    const float* bn2_g    = (const float*)d_in[11];
    const float* bn2_b    = (const float*)d_in[12];
    const float* W3       = (const float*)d_in[13];
    const float* b3       = (const float*)d_in[14];
    const float* pn       = (const float*)d_in[15];
    float* out = (float*)d_out;

    mlp_kernel<<<MB, 128>>>(features, bn0_g, bn0_b, W1, b1, bn1_g, bn1_b,
                            W2, b2, bn2_g, bn2_b, W3, b3, pn);
    scan_kernel<<<256, 256>>>(X, F, out);
}

// round 11
// speedup vs baseline: 1.0903x; 1.0691x over previous
#include <cuda_runtime.h>
#include <cuda_bf16.h>

#define FULLMASK 0xffffffffu
#define TT 4096

// ---- device scratch (allocation-free) ----
__device__ float g_p0[64][64];    // per-block feature col sum[32] + sumsq[32]
__device__ float g_p1[16][16];    // per-block h1 sum[8] + sumsq[8]
__device__ float g_p2[16][16];    // per-block h2 sum[8] + sumsq[8]
__device__ float g_h1[2048 * 8];
__device__ float g_h2[2048 * 8];

// ============ K1: bn0 column partial stats (64 x 256; 32 rows/block) ============
__global__ __launch_bounds__(256) void k_stats0(const float* __restrict__ features) {
    __shared__ float red[8][64];
    const int tid = threadIdx.x, warp = tid >> 5, lane = tid & 31;
    const float4* fp = (const float4*)(features + (size_t)blockIdx.x * 32 * 32);
    float4 v = __ldg(fp + tid);          // columns (tid%8)*4 .. +3
    float s0 = v.x, s1 = v.y, s2 = v.z, s3 = v.w;
    float q0 = v.x * v.x, q1 = v.y * v.y, q2 = v.z * v.z, q3 = v.w * v.w;
    #pragma unroll
    for (int d = 8; d <= 16; d <<= 1) {
        s0 += __shfl_xor_sync(FULLMASK, s0, d); s1 += __shfl_xor_sync(FULLMASK, s1, d);
        s2 += __shfl_xor_sync(FULLMASK, s2, d); s3 += __shfl_xor_sync(FULLMASK, s3, d);
        q0 += __shfl_xor_sync(FULLMASK, q0, d); q1 += __shfl_xor_sync(FULLMASK, q1, d);
        q2 += __shfl_xor_sync(FULLMASK, q2, d); q3 += __shfl_xor_sync(FULLMASK, q3, d);
    }
    if (lane < 8) {
        const int c = lane * 4;
        red[warp][c + 0] = s0; red[warp][c + 1] = s1;
        red[warp][c + 2] = s2; red[warp][c + 3] = s3;
        red[warp][32 + c + 0] = q0; red[warp][32 + c + 1] = q1;
        red[warp][32 + c + 2] = q2; red[warp][32 + c + 3] = q3;
    }
    __syncthreads();
    if (tid < 64) {
        float a = 0.f;
        #pragma unroll
        for (int w = 0; w < 8; w++) a += red[w][tid];
        g_p0[blockIdx.x][tid] = a;
    }
}

// ============ K2: finalize bn0, h1 = bn0(f) @ W1^T + b1, p1 partials (16 x 128) ============
__global__ __launch_bounds__(128) void k_h1(const float* __restrict__ features,
                                            const float* __restrict__ bn0_g,
                                            const float* __restrict__ bn0_b,
                                            const float* __restrict__ W1,
                                            const float* __restrict__ b1) {
    __shared__ float s_f[128][33];
    __shared__ float sW1[256], sb1[8];
    __shared__ float s_sc0[32], s_sh0[32];
    __shared__ float s_p[4][16];
    const int tid = threadIdx.x, warp = tid >> 5, lane = tid & 31;

    sW1[tid] = W1[tid];
    sW1[tid + 128] = W1[tid + 128];
    if (tid < 8) sb1[tid] = b1[tid];

    // stage own 128 rows (coalesced: lane = column)
    const float* fb = features + ((size_t)blockIdx.x * 128 + warp * 32) * 32;
    #pragma unroll 8
    for (int i = 0; i < 32; i++) s_f[warp * 32 + i][lane] = fb[i * 32 + lane];

    if (tid < 32) {
        float ss = 0.f, qq = 0.f;
        #pragma unroll 8
        for (int b = 0; b < 64; b++) { ss += g_p0[b][tid]; qq += g_p0[b][32 + tid]; }
        float mean = ss * (1.f / 2048.f);
        float var  = qq * (1.f / 2048.f) - mean * mean;
        float sc   = bn0_g[tid] * rsqrtf(var + 1e-5f);
        s_sc0[tid] = sc;
        s_sh0[tid] = bn0_b[tid] - mean * sc;
    }
    __syncthreads();

    float xn[32];
    #pragma unroll
    for (int c = 0; c < 32; c++) xn[c] = fmaf(s_f[tid][c], s_sc0[c], s_sh0[c]);
    float h[8];
    #pragma unroll
    for (int j = 0; j < 8; j++) {
        float a = sb1[j];
        #pragma unroll
        for (int c = 0; c < 32; c++) a = fmaf(sW1[j * 32 + c], xn[c], a);
        h[j] = a;
    }
    const int row = blockIdx.x * 128 + tid;
    float4* hp = (float4*)(g_h1 + row * 8);
    hp[0] = make_float4(h[0], h[1], h[2], h[3]);
    hp[1] = make_float4(h[4], h[5], h[6], h[7]);

    float sv[16];
    #pragma unroll
    for (int j = 0; j < 8; j++) { sv[j] = h[j]; sv[8 + j] = h[j] * h[j]; }
    #pragma unroll
    for (int d = 16; d; d >>= 1) {
        #pragma unroll
        for (int j = 0; j < 16; j++) sv[j] += __shfl_xor_sync(FULLMASK, sv[j], d);
    }
    if (lane < 16) s_p[warp][lane] = sv[lane];
    __syncthreads();
    if (tid < 16)
        g_p1[blockIdx.x][tid] = s_p[0][tid] + s_p[1][tid] + s_p[2][tid] + s_p[3][tid];
}

// ============ K3: finalize bn1, h2 = relu(bn1(h1)) @ W2^T + b2, p2 partials (16 x 128) ============
__global__ __launch_bounds__(128) void k_h2(const float* __restrict__ bn1_g,
                                            const float* __restrict__ bn1_b,
                                            const float* __restrict__ W2,
                                            const float* __restrict__ b2) {
    __shared__ float sW2[64], sb2[8];
    __shared__ float s_sc1[8], s_sh1[8];
    __shared__ float s_p[4][16];
    const int tid = threadIdx.x, warp = tid >> 5, lane = tid & 31;

    if (tid < 64) sW2[tid] = W2[tid];
    else if (tid < 72) sb2[tid - 64] = b2[tid - 64];
    if (tid < 8) {
        float ss = 0.f, qq = 0.f;
        #pragma unroll
        for (int b = 0; b < 16; b++) { ss += g_p1[b][tid]; qq += g_p1[b][8 + tid]; }
        float mean = ss * (1.f / 2048.f);
        float var  = qq * (1.f / 2048.f) - mean * mean;
        float sc   = bn1_g[tid] * rsqrtf(var + 1e-5f);
        s_sc1[tid] = sc;
        s_sh1[tid] = bn1_b[tid] - mean * sc;
    }
    __syncthreads();

    const int row = blockIdx.x * 128 + tid;
    const float4* hp = (const float4*)(g_h1 + row * 8);
    float4 v0 = hp[0], v1 = hp[1];
    float z[8] = {v0.x, v0.y, v0.z, v0.w, v1.x, v1.y, v1.z, v1.w};
    #pragma unroll
    for (int j = 0; j < 8; j++) z[j] = fmaxf(fmaf(z[j], s_sc1[j], s_sh1[j]), 0.f);
    float h[8];
    #pragma unroll
    for (int k = 0; k < 8; k++) {
        float a = sb2[k];
        #pragma unroll
        for (int j = 0; j < 8; j++) a = fmaf(sW2[k * 8 + j], z[j], a);
        h[k] = a;
    }
    float4* op = (float4*)(g_h2 + row * 8);
    op[0] = make_float4(h[0], h[1], h[2], h[3]);
    op[1] = make_float4(h[4], h[5], h[6], h[7]);

    float sv[16];
    #pragma unroll
    for (int j = 0; j < 8; j++) { sv[j] = h[j]; sv[8 + j] = h[j] * h[j]; }
    #pragma unroll
    for (int d = 16; d; d >>= 1) {
        #pragma unroll
        for (int j = 0; j < 16; j++) sv[j] += __shfl_xor_sync(FULLMASK, sv[j], d);
    }
    if (lane < 16) s_p[warp][lane] = sv[lane];
    __syncthreads();
    if (tid < 16)
        g_p2[blockIdx.x][tid] = s_p[0][tid] + s_p[1][tid] + s_p[2][tid] + s_p[3][tid];
}

// ============ K4: bn2 finalize + params + 2-warp-per-row IIR scan (512 x 256) ============
// Block = 4 rows x 2 warps. Chunk c = half*32 + lane covers steps [64c, 64c+64)
// in closed affine form (transform [[p,0],[r,p]] + offset (q1,q2)); weighted
// output accumulators (a1,a2,bt,ws) are affine in the chunk's entry state.
__global__ __launch_bounds__(256) void k_scan(const float* __restrict__ X,
                                              const float* __restrict__ Fp,
                                              const float* __restrict__ bn2_g,
                                              const float* __restrict__ bn2_b,
                                              const float* __restrict__ W3,
                                              const float* __restrict__ b3,
                                              const float* __restrict__ pn,
                                              float* __restrict__ out) {
    __shared__ float sW3[48], sb3[6], spn[6];
    __shared__ float s_sc2[8], s_sh2[8];
    __shared__ float s_T[4][4];
    __shared__ float s_red[8][2];

    const int tid  = threadIdx.x;
    const int warp = tid >> 5;
    const int lane = tid & 31;
    const int rowl = warp & 3;
    const int half = warp >> 2;
    const int row  = blockIdx.x * 4 + rowl;

    if (tid < 48) sW3[tid] = W3[tid];
    else if (tid < 54) sb3[tid - 48] = b3[tid - 48];
    else if (tid < 60) spn[tid - 54] = pn[tid - 54];
    if (tid < 8) {
        float ss = 0.f, qq = 0.f;
        #pragma unroll
        for (int b = 0; b < 16; b++) { ss += g_p2[b][tid]; qq += g_p2[b][8 + tid]; }
        float mean = ss * (1.f / 2048.f);
        float var  = qq * (1.f / 2048.f) - mean * mean;
        float sc   = bn2_g[tid] * rsqrtf(var + 1e-5f);
        s_sc2[tid] = sc;
        s_sh2[tid] = bn2_b[tid] - mean * sc;
    }
    __syncthreads();

    // per-row params (redundant across the row's 2 warps / 32 lanes; ~100 instr)
    const float4* hp = (const float4*)(g_h2 + row * 8);
    const float4 v0 = hp[0], v1 = hp[1];
    float z[8] = {v0.x, v0.y, v0.z, v0.w, v1.x, v1.y, v1.z, v1.w};
    #pragma unroll
    for (int j = 0; j < 8; j++) z[j] = fmaxf(fmaf(z[j], s_sc2[j], s_sh2[j]), 0.f);
    float sg[6];
    #pragma unroll
    for (int j = 0; j < 6; j++) {
        float a = sb3[j] + spn[j];
        #pragma unroll
        for (int k = 0; k < 8; k++) a = fmaf(sW3[j * 8 + k], z[k], a);
        sg[j] = __fdividef(1.f, 1.f + __expf(-a));
    }
    const float f_start = fmaf(4.5f,  sg[0], 0.5f);
    const float f_inf   = fmaf(0.49f, sg[1], 0.01f);
    const float f_decay = 2.f * sg[2];
    const float f_T     = 2.f * sg[3];
    const float w_off   = sg[4];
    const float w_T     = fmaf(0.49f, sg[5], 0.01f);

    const float df  = f_start - f_inf;
    const float lnD = fmaf(-2.30258509f, f_decay, -0.35667494f);  // ln(0.7*0.1^fd)
    const float H   = 10.f * __expf(-2.30258509f * f_T);          // 10*0.1^fT
    const float kf  = __fdividef(lnD, 4096.f * H);
    const float G   = __expf(kf);
    const float z0  = __fdividef(w_off, w_T);
    const float lw  = -__fdividef(1.f, 4096.f * w_T);
    const float R   = __expf(lw);
    const float cc  = 0.16228221f * __ldg(Fp);   // sqrt(2^(1/3)-1)*F/pi

    // ---- scan ----
    const float* xrow = X + (size_t)row * TT;
    const int c  = half * 32 + lane;
    const int t0 = c << 6;
    float g = __expf(kf * (float)t0);
    float e = __expf(fmaf(lw, (float)t0, z0));   // may be inf -> w = 0 (correct)
    float xp = __ldcs(xrow + (t0 ? t0 - 1 : 0));
    const float y0 = __ldg(xrow);

    float p = 1.f, r = 0.f, q1 = 0.f, q2 = 0.f;
    float a1 = 0.f, a2 = 0.f, bt = 0.f, ws = 0.f;

    const float4* xv = (const float4*)(xrow + t0);
    float4 v = __ldcs(xv);

#define STEP(xval) do {                               \
    float w_ = __fdividef(1.f, 1.f + e);              \
    float f_ = fmaf(df, g, f_inf);                    \
    float i_ = __fdividef(1.f, cc + f_);              \
    float b_ = f_ * i_;                               \
    float ap = fmaf(-2.f, b_, 1.f);                   \
    g *= G; e *= R;                                   \
    float m_ = fmaf(b_, ap, b_);                      \
    float xx = (xval) + xp;                           \
    float u1 = b_ * xx;                               \
    float u2 = b_ * u1;                               \
    float pm = m_ * p;                                \
    float t2 = fmaf(m_, q1, u2);                      \
    p = ap * p;                                       \
    r = fmaf(ap, r, pm);                              \
    q1 = fmaf(ap, q1, u1);                            \
    q2 = fmaf(ap, q2, t2);                            \
    a1 = fmaf(w_, r, a1);                             \
    a2 = fmaf(w_, p, a2);                             \
    bt = fmaf(w_, q2, bt);                            \
    ws += w_;                                         \
    xp = (xval);                                      \
  } while (0)

    if (c == 0) {
        // t = 0: y2_0 = y0 passes through identity -> a2 += w0, ws += w0
        float w0 = __fdividef(1.f, 1.f + e);
        a2 = w0; ws = w0;
        g *= G; e *= R;
        // xp stays X[0] for the t=1 step
    } else {
        STEP(v.x);
    }
    STEP(v.y); STEP(v.z); STEP(v.w);
    #pragma unroll 4
    for (int i = 1; i < 16; i++) {
        v = __ldcs(xv + i);
        STEP(v.x); STEP(v.y); STEP(v.z); STEP(v.w);
    }
#undef STEP

    // intra-warp inclusive scan (compose self with prefix from lower lanes)
    #pragma unroll
    for (int d = 1; d < 32; d <<= 1) {
        float pL  = __shfl_up_sync(FULLMASK, p,  d);
        float rL  = __shfl_up_sync(FULLMASK, r,  d);
        float q1L = __shfl_up_sync(FULLMASK, q1, d);
        float q2L = __shfl_up_sync(FULLMASK, q2, d);
        if (lane >= d) {
            float pn2 = p * pL;
            float rn  = fmaf(r, pL, p * rL);
            float q1n = fmaf(p, q1L, q1);
            float q2n = fmaf(r, q1L, fmaf(p, q2L, q2));
            p = pn2; r = rn; q1 = q1n; q2 = q2n;
        }
    }
    // publish half-0 total (lane 31 inclusive) for half-1
    if (half == 0 && lane == 31) {
        s_T[rowl][0] = p; s_T[rowl][1] = r; s_T[rowl][2] = q1; s_T[rowl][3] = q2;
    }
    // exclusive shift (identity into lane 0)
    float pe  = __shfl_up_sync(FULLMASK, p,  1);
    float re  = __shfl_up_sync(FULLMASK, r,  1);
    float q1e = __shfl_up_sync(FULLMASK, q1, 1);
    float q2e = __shfl_up_sync(FULLMASK, q2, 1);
    if (lane == 0) { pe = 1.f; re = 0.f; q1e = 0.f; q2e = 0.f; }
    __syncthreads();
    if (half == 1) {   // compose exclusive prefix with half-0 total (applied first)
        const float pA  = s_T[rowl][0], rA  = s_T[rowl][1];
        const float q1A = s_T[rowl][2], q2A = s_T[rowl][3];
        float pn2 = pe * pA;
        float rn  = fmaf(re, pA, pe * rA);
        float q1n = fmaf(pe, q1A, q1e);
        float q2n = fmaf(re, q1A, fmaf(pe, q2A, q2e));
        pe = pn2; re = rn; q1e = q1n; q2e = q2n;
    }

    const float y1i = fmaf(pe, y0, q1e);
    const float y2i = fmaf(re + pe, y0, q2e);
    float contrib = fmaf(a1, y1i, fmaf(a2, y2i, bt));

    #pragma unroll
    for (int d = 16; d; d >>= 1) {
        contrib += __shfl_xor_sync(FULLMASK, contrib, d);
        ws      += __shfl_xor_sync(FULLMASK, ws, d);
    }
    if (lane == 0) { s_red[warp][0] = contrib; s_red[warp][1] = ws; }
    __syncthreads();
    if (half == 0 && lane == 0)
        out[row] = (s_red[warp][0] + s_red[warp + 4][0]) /
                   (s_red[warp][1] + s_red[warp + 4][1]);
}

extern "C" void kernel_launch(void* const* d_in, const int* in_sizes, int n_in,
                              void* d_out, int out_size) {
    const float* X        = (const float*)d_in[0];
    const float* features = (const float*)d_in[1];
    const float* F        = (const float*)d_in[2];
    const float* bn0_g    = (const float*)d_in[3];
    const float* bn0_b    = (const float*)d_in[4];
    const float* W1       = (const float*)d_in[5];
    const float* b1       = (const float*)d_in[6];
    const float* bn1_g    = (const float*)d_in[7];
    const float* bn1_b    = (const float*)d_in[8];
    const float* W2       = (const float*)d_in[9];
    const float* b2       = (const float*)d_in[10];
    const float* bn2_g    = (const float*)d_in[11];
    const float* bn2_b    = (const float*)d_in[12];
    const float* W3       = (const float*)d_in[13];
    const float* b3       = (const float*)d_in[14];
    const float* pn       = (const float*)d_in[15];
    float* out = (float*)d_out;

    k_stats0<<<64, 256>>>(features);
    k_h1<<<16, 128>>>(features, bn0_g, bn0_b, W1, b1);
    k_h2<<<16, 128>>>(bn1_g, bn1_b, W2, b2);
    k_scan<<<512, 256>>>(X, F, bn2_g, bn2_b, W3, b3, pn, out);
}